// round 15
// baseline (speedup 1.0000x reference)
#include <cuda_runtime.h>
#include <cuda_bf16.h>

// out[b,t,v] = sum_d x[b,t,d,v] * w[d] + bias
// x: (2, 512, 8, 32000) fp32 contiguous; w: (8,); b: (1,)
// out: (2, 512, 32000) fp32
//
// FINAL kernel — converged at the HBM roofline: ~90% of sustained DRAM
// peak (7.13-7.16 TB/s), best measured 164.35 us, rel_err 0.
//
// Complete measured decision record (R1-R13, every axis probed with a
// prediction before the bench):
//  - 1 thread per float4 of output; 8 front-batched independent float4
//    loads (MLP=8) fully hide DRAM latency; 512B coalesced per warp per
//    depth row.
//  - dense one-shot grid of 32000x256: block rasterization keeps the
//    concurrent address footprint compact -> DRAM page locality.
//      * persistent grid-stride:  85.4% DRAM (regression, R7)
//      * 2x float4/thread MLP=16: 89.5% DRAM (R9)
//      * 512-thread blocks:       89.6% DRAM (R11)
//      * 128-thread blocks:       89.7% DRAM, occ 90.8% -> DRAM flat:
//        SM-side latency tolerance has slack; HBM is the only wall (R13)
//  - exact grid 32000*256 == 8,192,000 outputs: no tail predicate.
//  - __ldcs/__stcs: measured neutral, kept (zero-reuse stream).
// Residual ~10% to spec = 8:1 R/W bus turnaround + refresh; not
// kernel-addressable. Compute pipes idle by design (AI = 0.44 FLOP/B).

#define DEPTH   8
#define VROW4   8000                    // 32000 floats / 4 per (b,t,d) row

__global__ __launch_bounds__(256) void ttm_kernel(
    const float4* __restrict__ x,
    const float*  __restrict__ w,
    const float*  __restrict__ bias,
    float4* __restrict__ out)
{
    long i = (long)blockIdx.x * 256 + threadIdx.x;   // grid is exact: no bounds check

    int row = (int)(i / VROW4);   // which (b,t) of 1024
    int v4  = (int)(i % VROW4);

    // weights: tiny, L1/L2-broadcast; registers for the whole kernel
    float wr[DEPTH];
#pragma unroll
    for (int d = 0; d < DEPTH; ++d) wr[d] = __ldg(&w[d]);
    const float bb = __ldg(bias);

    const float4* p = x + (long)row * DEPTH * VROW4 + v4;

    // Front-batch all 8 independent streaming loads (MLP=8)
    float4 t[DEPTH];
#pragma unroll
    for (int d = 0; d < DEPTH; ++d)
        t[d] = __ldcs(p + (long)d * VROW4);          // evict-first: zero reuse

    float4 acc;
    acc.x = bb; acc.y = bb; acc.z = bb; acc.w = bb;

#pragma unroll
    for (int d = 0; d < DEPTH; ++d) {
        acc.x = fmaf(t[d].x, wr[d], acc.x);
        acc.y = fmaf(t[d].y, wr[d], acc.y);
        acc.z = fmaf(t[d].z, wr[d], acc.z);
        acc.w = fmaf(t[d].w, wr[d], acc.w);
    }

    __stcs(&out[i], acc);                            // streaming store
}

extern "C" void kernel_launch(void* const* d_in, const int* in_sizes, int n_in,
                              void* d_out, int out_size)
{
    const float4* x    = (const float4*)d_in[0];
    const float*  w    = (const float*) d_in[1];
    const float*  bias = (const float*) d_in[2];
    float4*       out  = (float4*)      d_out;

    ttm_kernel<<<32000, 256>>>(x, w, bias, out);
}

// round 16
// speedup vs baseline: 1.0008x; 1.0008x over previous
#include <cuda_runtime.h>
#include <cuda_bf16.h>

// out[b,t,v] = sum_d x[b,t,d,v] * w[d] + bias
// x: (2, 512, 8, 32000) fp32 contiguous; w: (8,); b: (1,)
// out: (2, 512, 32000) fp32
//
// CONVERGED HBM-roofline kernel: 89-90% of sustained DRAM peak
// (7.07-7.16 TB/s), 164.35-166 us across five runs (run variance ~1%).
//
// Complete measured decision record (R1-R14):
//  - 1 thread per float4; 8 front-batched independent float4 loads
//    (MLP=8); 512B coalesced per warp per depth row.
//  - dense one-shot grid 32000x256 (rasterization -> DRAM page locality):
//      * persistent grid-stride:  85.4% DRAM (regression)
//      * 2x float4/thread MLP=16: 89.5% DRAM
//      * 512-thr blocks: 89.6% | 128-thr blocks: 89.7% (occ 91%, DRAM
//        flat -> HBM controller is the sole binding resource)
//  - exact grid 32000*256 == 8,192,000 outputs: no tail predicate.
//  - __ldcs/__stcs: neutral, kept (zero-reuse stream).
//  - R15: 32-bit index math (TOTAL4 < 2^31) — free preamble cleanup.
// Residual ~10% to spec = 8:1 R/W bus turnaround + refresh (physics).

#define DEPTH   8
#define VROW4   8000                    // 32000 floats / 4 per (b,t,d) row

__global__ __launch_bounds__(256) void ttm_kernel(
    const float4* __restrict__ x,
    const float*  __restrict__ w,
    const float*  __restrict__ bias,
    float4* __restrict__ out)
{
    // TOTAL4 = 8,192,000 < 2^31: full 32-bit index arithmetic
    unsigned i = blockIdx.x * 256u + threadIdx.x;    // grid exact: no bounds check

    unsigned row = i / VROW4;     // which (b,t) of 1024
    unsigned v4  = i % VROW4;

    // weights: tiny, L1/L2-broadcast; registers for the whole kernel
    float wr[DEPTH];
#pragma unroll
    for (int d = 0; d < DEPTH; ++d) wr[d] = __ldg(&w[d]);
    const float bb = __ldg(bias);

    const float4* p = x + (size_t)row * (DEPTH * VROW4) + v4;

    // Front-batch all 8 independent streaming loads (MLP=8)
    float4 t[DEPTH];
#pragma unroll
    for (int d = 0; d < DEPTH; ++d)
        t[d] = __ldcs(p + d * VROW4);                // evict-first: zero reuse

    float4 acc;
    acc.x = bb; acc.y = bb; acc.z = bb; acc.w = bb;

#pragma unroll
    for (int d = 0; d < DEPTH; ++d) {
        acc.x = fmaf(t[d].x, wr[d], acc.x);
        acc.y = fmaf(t[d].y, wr[d], acc.y);
        acc.z = fmaf(t[d].z, wr[d], acc.z);
        acc.w = fmaf(t[d].w, wr[d], acc.w);
    }

    __stcs(&out[i], acc);                            // streaming store
}

extern "C" void kernel_launch(void* const* d_in, const int* in_sizes, int n_in,
                              void* d_out, int out_size)
{
    const float4* x    = (const float4*)d_in[0];
    const float*  w    = (const float*) d_in[1];
    const float*  bias = (const float*) d_in[2];
    float4*       out  = (float4*)      d_out;

    ttm_kernel<<<32000, 256>>>(x, w, bias, out);
}

// round 17
// speedup vs baseline: 1.0012x; 1.0004x over previous
#include <cuda_runtime.h>
#include <cuda_bf16.h>

// out[b,t,v] = sum_d x[b,t,d,v] * w[d] + bias
// x: (2, 512, 8, 32000) fp32 contiguous; w: (8,); b: (1,)
// out: (2, 512, 32000) fp32
//
// FINAL CONVERGED KERNEL — HBM roofline: 89-90% of sustained DRAM peak
// (7.07-7.16 TB/s), 164.35-166 us across six runs (~1% run variance).
//
// Complete measured decision record (R1-R15, predict-then-verify on
// every axis):
//  - 1 thread per float4; 8 front-batched independent float4 loads
//    (MLP=8) hide DRAM latency; 512B coalesced per warp per depth row.
//  - dense one-shot grid 32000x256 (rasterization -> DRAM page locality):
//      * persistent grid-stride:  85.4% DRAM (regression, R7)
//      * 2x float4/thread MLP=16: 89.5% DRAM (R9)
//      * 512-thr blocks: 89.6% (R11) | 128-thr: 89.7%, occ 91% with DRAM
//        flat -> HBM controller is the sole binding resource (R13)
//  - exact grid 32000*256 == 8,192,000 outputs: no tail predicate.
//  - __ldcs/__stcs: measured neutral, kept (zero-reuse stream).
//  - 32-bit index math: ALU 2.8%->0.5%, time flat (R15) — kept, leaner.
// Residual ~10% to spec = 8:1 R/W bus turnaround + refresh (physics).
// Compute pipes idle by design (AI = 0.44 FLOP/B).

#define DEPTH   8
#define VROW4   8000                    // 32000 floats / 4 per (b,t,d) row

__global__ __launch_bounds__(256) void ttm_kernel(
    const float4* __restrict__ x,
    const float*  __restrict__ w,
    const float*  __restrict__ bias,
    float4* __restrict__ out)
{
    // TOTAL4 = 8,192,000 < 2^31: full 32-bit index arithmetic
    unsigned i = blockIdx.x * 256u + threadIdx.x;    // grid exact: no bounds check

    unsigned row = i / VROW4;     // which (b,t) of 1024
    unsigned v4  = i % VROW4;

    // weights: tiny, L1/L2-broadcast; registers for the whole kernel
    float wr[DEPTH];
#pragma unroll
    for (int d = 0; d < DEPTH; ++d) wr[d] = __ldg(&w[d]);
    const float bb = __ldg(bias);

    const float4* p = x + (size_t)row * (DEPTH * VROW4) + v4;

    // Front-batch all 8 independent streaming loads (MLP=8)
    float4 t[DEPTH];
#pragma unroll
    for (int d = 0; d < DEPTH; ++d)
        t[d] = __ldcs(p + d * VROW4);                // evict-first: zero reuse

    float4 acc;
    acc.x = bb; acc.y = bb; acc.z = bb; acc.w = bb;

#pragma unroll
    for (int d = 0; d < DEPTH; ++d) {
        acc.x = fmaf(t[d].x, wr[d], acc.x);
        acc.y = fmaf(t[d].y, wr[d], acc.y);
        acc.z = fmaf(t[d].z, wr[d], acc.z);
        acc.w = fmaf(t[d].w, wr[d], acc.w);
    }

    __stcs(&out[i], acc);                            // streaming store
}

extern "C" void kernel_launch(void* const* d_in, const int* in_sizes, int n_in,
                              void* d_out, int out_size)
{
    const float4* x    = (const float4*)d_in[0];
    const float*  w    = (const float*) d_in[1];
    const float*  bias = (const float*) d_in[2];
    float4*       out  = (float4*)      d_out;

    ttm_kernel<<<32000, 256>>>(x, w, bias, out);
}